// round 2
// baseline (speedup 1.0000x reference)
#include <cuda_runtime.h>
#include <cuda_bf16.h>

// Problem constants
#define B_   256
#define S_   2048
#define VOCAB_ 10
#define E_   32
#define H_   64
#define OUT_ 10

#define NTAB (VOCAB_ * VOCAB_)       // 100 combined-index table rows
#define CHUNK 16                      // steps buffered before logits flush
#define NCHUNK (S_ / CHUNK)           // 128
#define HS 68                         // padded row stride for h buffer (bank-conflict-free)

// Scratch (no cudaMalloc allowed). 16B-aligned for vector loads.
__device__ __align__(16) float g_table[NTAB * H_];     // 25.6 KB
__device__ __align__(16) unsigned char g_idx[B_ * S_]; // 512 KB

// ---------------------------------------------------------------------------
// Kernel A: build the 100x64 input-projection table
// T[v][j] = b[j] + sum_e embed[v1][e]*Wx[e][j] + embed[v2][e]*Wx[32+e][j]
// ---------------------------------------------------------------------------
__global__ void build_table_kernel(const float* __restrict__ embed,
                                   const float* __restrict__ Wx,
                                   const float* __restrict__ bvec) {
    int v = blockIdx.x;           // 0..99
    int j = threadIdx.x;          // 0..63
    int v1 = v / VOCAB_;
    int v2 = v % VOCAB_;
    float acc = bvec[j];
    #pragma unroll
    for (int e = 0; e < E_; ++e) {
        acc = fmaf(embed[v1 * E_ + e], Wx[e * H_ + j], acc);
        acc = fmaf(embed[v2 * E_ + e], Wx[(E_ + e) * H_ + j], acc);
    }
    g_table[v * H_ + j] = acc;
}

// ---------------------------------------------------------------------------
// Kernel B: compact (num1,num2) -> uint8 combined index
// ---------------------------------------------------------------------------
__global__ void build_idx_kernel(const int* __restrict__ num1,
                                 const int* __restrict__ num2, int n) {
    int i = blockIdx.x * blockDim.x + threadIdx.x;
    if (i < n) {
        g_idx[i] = (unsigned char)(num1[i] * VOCAB_ + num2[i]);
    }
}

// ---------------------------------------------------------------------------
// Kernel C: the fused RNN + logits kernel.
// 128 threads/CTA = 2 chains (batch rows) of 64 threads each.
// Thread j of a chain owns h_j and column j of Wh (64 registers).
// h exchanged via a 16-row shared ring buffer; logits flushed every 16 steps.
// ---------------------------------------------------------------------------
__global__ void __launch_bounds__(128, 1)
rnn_kernel(const float* __restrict__ Wh,
           const float* __restrict__ Wd,
           const float* __restrict__ bd,
           float* __restrict__ out) {
    __shared__ __align__(16) float T_sh[NTAB * H_];            // 25600 B
    __shared__ __align__(16) float Wd_sh[H_ * OUT_];           // 2560 B
    __shared__ float bd_sh[OUT_];
    __shared__ __align__(16) float hbuf[2][CHUNK * HS];        // 2 chains x 16 x 68
    __shared__ __align__(16) unsigned char idxb[2][2 * CHUNK]; // double-buffered idx

    const int tid   = threadIdx.x;
    const int chain = tid >> 6;        // 0 or 1
    const int j     = tid & 63;        // lane within chain = h index
    const int b     = blockIdx.x * 2 + chain;

    // --- cooperative load of the table + Wd + bd into shared ---
    for (int i = tid; i < NTAB * H_; i += 128) T_sh[i] = g_table[i];
    for (int i = tid; i < H_ * OUT_; i += 128) Wd_sh[i] = Wd[i];
    if (tid < OUT_) bd_sh[tid] = bd[tid];

    // --- Wh column j into registers ---
    float wh[H_];
    #pragma unroll
    for (int k = 0; k < H_; ++k) wh[k] = Wh[k * H_ + j];

    // --- init h ring: row CHUNK-1 = h_{-1} = 0 ---
    hbuf[chain][(CHUNK - 1) * HS + j] = 0.0f;

    // --- prologue: load idx chunk 0 directly into shared ---
    const unsigned char* idx_g = &g_idx[(size_t)b * S_];
    if (j == 0) {
        int4 v = *reinterpret_cast<const int4*>(idx_g);
        *reinterpret_cast<int4*>(&idxb[chain][0]) = v;
    }
    __syncthreads();

    int4 nextidx;

    for (int c = 0; c < NCHUNK; ++c) {
        // prefetch next chunk's indices (latency hidden by 16 steps of work)
        if (j == 0 && c + 1 < NCHUNK) {
            nextidx = *reinterpret_cast<const int4*>(idx_g + (c + 1) * CHUNK);
        }
        const unsigned char* ib = &idxb[chain][(c & 1) * CHUNK];

        #pragma unroll 1
        for (int t = 0; t < CHUNK; ++t) {
            const int cur  = t;
            const int prev = (t + CHUNK - 1) & (CHUNK - 1);
            const int idx  = (int)ib[t];

            // 4 independent accumulator chains to break FMA latency
            float a0 = T_sh[idx * H_ + j];
            float a1 = 0.0f, a2 = 0.0f, a3 = 0.0f;
            const float4* hp4 =
                reinterpret_cast<const float4*>(&hbuf[chain][prev * HS]);
            #pragma unroll
            for (int k4 = 0; k4 < H_ / 4; ++k4) {
                float4 hv = hp4[k4];
                a0 = fmaf(hv.x, wh[4 * k4 + 0], a0);
                a1 = fmaf(hv.y, wh[4 * k4 + 1], a1);
                a2 = fmaf(hv.z, wh[4 * k4 + 2], a2);
                a3 = fmaf(hv.w, wh[4 * k4 + 3], a3);
            }
            float hj = tanhf((a0 + a1) + (a2 + a3));
            hbuf[chain][cur * HS + j] = hj;
            __syncthreads();
        }

        // --- logits for this chunk: [16,64] @ [64,10] + bd ---
        const int s0 = c * CHUNK;
        for (int i = j; i < CHUNK * OUT_; i += H_) {
            const int t = i / OUT_;
            const int o = i - t * OUT_;
            const float* hr = &hbuf[chain][t * HS];
            float acc0 = bd_sh[o], acc1 = 0.0f;
            #pragma unroll
            for (int k = 0; k < H_; k += 2) {
                acc0 = fmaf(hr[k],     Wd_sh[k * OUT_ + o],       acc0);
                acc1 = fmaf(hr[k + 1], Wd_sh[(k + 1) * OUT_ + o], acc1);
            }
            out[((size_t)b * S_ + (s0 + t)) * OUT_ + o] = acc0 + acc1;
        }

        // publish next chunk's indices, then barrier protects both
        // (a) hbuf reuse and (b) idx visibility
        if (j == 0 && c + 1 < NCHUNK) {
            *reinterpret_cast<int4*>(&idxb[chain][((c + 1) & 1) * CHUNK]) = nextidx;
        }
        __syncthreads();
    }
}

// ---------------------------------------------------------------------------
// Entry point
// Inputs (metadata order): num1[i32 B*S], num2[i32 B*S], embed[f32 10*32],
// Wx[f32 64*64], Wh[f32 64*64], b[f32 64], Wd[f32 64*10], bd[f32 10]
// Output: float32 [B, S, 10]
// ---------------------------------------------------------------------------
extern "C" void kernel_launch(void* const* d_in, const int* in_sizes, int n_in,
                              void* d_out, int out_size) {
    const int*   num1  = (const int*)d_in[0];
    const int*   num2  = (const int*)d_in[1];
    const float* embed = (const float*)d_in[2];
    const float* Wx    = (const float*)d_in[3];
    const float* Wh    = (const float*)d_in[4];
    const float* bvec  = (const float*)d_in[5];
    const float* Wd    = (const float*)d_in[6];
    const float* bd    = (const float*)d_in[7];
    float* out = (float*)d_out;

    build_table_kernel<<<NTAB, H_>>>(embed, Wx, bvec);

    const int n = B_ * S_;
    build_idx_kernel<<<(n + 255) / 256, 256>>>(num1, num2, n);

    rnn_kernel<<<B_ / 2, 128>>>(Wh, Wd, bd, out);
}